// round 3
// baseline (speedup 1.0000x reference)
#include <cuda_runtime.h>
#include <math.h>

// ---------------- scratch (device globals; no allocation) ----------------
__device__ float g_p1[256*14*14*256];    // conv1+pool output   [256,14,14,256]
__device__ float g_c2[256*14*14*256];    // conv2 output (relu) [256,14,14,256]
__device__ float g_feat[256*12544];      // pooled+flattened     [256,12544]
__device__ float g_z[512*64];            // rows 0..255: z_e, 256..511: z_q
__device__ float g_dech[512*12544];      // dec matmul output    [512,7,7,256]
__device__ float g_u1[512*14*14*256];    // deconv1 output(relu) [512,14,14,256]

// ---------------- conv1 (4x4,1->256, SAME) + relu + maxpool2x2 ----------------
__global__ void k_conv1_pool(const float* __restrict__ x,
                             const float* __restrict__ w1,
                             const float* __restrict__ b1) {
    int b  = blockIdx.x;
    int pr0 = blockIdx.y * 2;
    int co = threadIdx.x;
    __shared__ float xs[784];
    for (int i = threadIdx.x; i < 784; i += 256) xs[i] = x[b*784 + i];
    __syncthreads();
    float w[16];
#pragma unroll
    for (int t = 0; t < 16; t++) w[t] = w1[t*256 + co];
    float bias = b1[co];
    for (int pr = pr0; pr < pr0 + 2; pr++)
        for (int pc = 0; pc < 14; pc++) {
            float m = 0.f;   // max(relu(v)) == max(0, max(v))
#pragma unroll
            for (int dy = 0; dy < 2; dy++)
#pragma unroll
            for (int dx = 0; dx < 2; dx++) {
                int y = pr*2 + dy, xx = pc*2 + dx;
                float s = bias;
#pragma unroll
                for (int kh = 0; kh < 4; kh++) {
                    int iy = y - 1 + kh;
                    if ((unsigned)iy < 28u) {
#pragma unroll
                        for (int kw = 0; kw < 4; kw++) {
                            int ix = xx - 1 + kw;
                            if ((unsigned)ix < 28u)
                                s = fmaf(w[kh*4 + kw], xs[iy*28 + ix], s);
                        }
                    }
                }
                m = fmaxf(m, s);
            }
            g_p1[((b*14 + pr)*14 + pc)*256 + co] = m;
        }
}

// ---------------- implicit-GEMM conv (4x4, 256->256, SAME, logical 14x14) ----------------
// UPS=0: in = g_p1 (14x14 phys), out = g_c2.   conv2 path.
// UPS=1: in = g_dech (7x7 phys, nearest-upsampled 2x), out = g_u1. deconv1 path.
// M = gridDim.x*128 rows of (b, r, c) conv positions; N=256 (2 tiles of 128); K=4096.
// Epilogue: +bias, relu.
template<int UPS>
__global__ __launch_bounds__(256) void k_conv_gemm(const float* __restrict__ wt,
                                                   const float* __restrict__ bias) {
    const float* in = UPS ? g_dech : g_p1;
    float*      out = UPS ? g_u1   : g_c2;
    const int S = UPS ? 7 : 14;

    __shared__ float As[2][128*20];   // [m][k] k padded 16->20
    __shared__ float Bs[2][16*128];   // [k][n]

    int tid = threadIdx.x;
    int mt = blockIdx.x, nt = blockIdx.y;

    // A loader: thread loads rows (a_row, a_row+64), 4 consecutive k each
    int a_k4  = tid & 3;
    int a_row = tid >> 2;
    int ar[2], ac[2];
    const float* abase[2];
#pragma unroll
    for (int i = 0; i < 2; i++) {
        int m = mt*128 + a_row + 64*i;
        int b = m / 196; int rem = m - b*196;
        int r = rem / 14; int c = rem - r*14;
        ar[i] = r; ac[i] = c;
        abase[i] = in + (size_t)b * (S*S*256);
    }
    // B loader: rows (b_k, b_k+8), 4 consecutive n each
    int b_n4 = tid & 31;
    int b_k  = tid >> 5;
    const float* wbase = wt + nt*128 + b_n4*4;

    int row_t = tid >> 4, col_t = tid & 15;

    float acc[8][8];
#pragma unroll
    for (int e = 0; e < 8; e++)
#pragma unroll
        for (int f = 0; f < 8; f++) acc[e][f] = 0.f;

    float4 av[2], bv[2];
    auto doLoad = [&](int kt) {
        int khw = kt >> 4, kh = khw >> 2, kw = khw & 3;
        int cib = (kt & 15)*16 + a_k4*4;
#pragma unroll
        for (int i = 0; i < 2; i++) {
            int iy = ar[i] - 1 + kh, ix = ac[i] - 1 + kw;
            float4 v = make_float4(0.f, 0.f, 0.f, 0.f);
            if (((unsigned)iy < 14u) && ((unsigned)ix < 14u))
                v = *reinterpret_cast<const float4*>(
                        abase[i] + ((iy >> UPS)*S + (ix >> UPS))*256 + cib);
            av[i] = v;
        }
        const float* p = wbase + (kt*16 + b_k)*256;
        bv[0] = *reinterpret_cast<const float4*>(p);
        bv[1] = *reinterpret_cast<const float4*>(p + 8*256);
    };
    auto doStore = [&](int buf) {
        *reinterpret_cast<float4*>(&As[buf][a_row*20 + a_k4*4])       = av[0];
        *reinterpret_cast<float4*>(&As[buf][(a_row+64)*20 + a_k4*4])  = av[1];
        *reinterpret_cast<float4*>(&Bs[buf][b_k*128 + b_n4*4])        = bv[0];
        *reinterpret_cast<float4*>(&Bs[buf][(b_k+8)*128 + b_n4*4])    = bv[1];
    };

    doLoad(0); doStore(0); __syncthreads();

    for (int kt = 0; kt < 256; kt++) {
        int cur = kt & 1;
        if (kt < 255) doLoad(kt + 1);
#pragma unroll
        for (int k = 0; k < 16; k++) {
            float a[8], bb[8];
#pragma unroll
            for (int e = 0; e < 4; e++) {
                a[e]   = As[cur][(row_t*4 + e)*20 + k];
                a[4+e] = As[cur][(64 + row_t*4 + e)*20 + k];
            }
            float4 q0 = *reinterpret_cast<const float4*>(&Bs[cur][k*128 + col_t*4]);
            float4 q1 = *reinterpret_cast<const float4*>(&Bs[cur][k*128 + 64 + col_t*4]);
            bb[0]=q0.x; bb[1]=q0.y; bb[2]=q0.z; bb[3]=q0.w;
            bb[4]=q1.x; bb[5]=q1.y; bb[6]=q1.z; bb[7]=q1.w;
#pragma unroll
            for (int e = 0; e < 8; e++)
#pragma unroll
                for (int f = 0; f < 8; f++)
                    acc[e][f] = fmaf(a[e], bb[f], acc[e][f]);
        }
        if (kt < 255) { doStore(cur ^ 1); __syncthreads(); }
    }

    // epilogue: bias + relu, vectorized stores
    int m0 = mt*128;
#pragma unroll
    for (int e = 0; e < 8; e++) {
        int mrow = m0 + ((e < 4) ? (row_t*4 + e) : (64 + row_t*4 + e - 4));
        float* op = out + (size_t)mrow*256 + nt*128;
#pragma unroll
        for (int h = 0; h < 2; h++) {
            int n0 = h*64 + col_t*4;
            float4 bz = *reinterpret_cast<const float4*>(bias + nt*128 + n0);
            float4 v;
            v.x = fmaxf(acc[e][h*4+0] + bz.x, 0.f);
            v.y = fmaxf(acc[e][h*4+1] + bz.y, 0.f);
            v.z = fmaxf(acc[e][h*4+2] + bz.z, 0.f);
            v.w = fmaxf(acc[e][h*4+3] + bz.w, 0.f);
            *reinterpret_cast<float4*>(op + n0) = v;
        }
    }
}

// ---------------- maxpool 14->7 + flatten ----------------
__global__ void k_pool2() {
    int idx = blockIdx.x*256 + threadIdx.x;     // 256*49*256 total
    int co = idx & 255;
    int rest = idx >> 8;
    int pc = rest % 7; int t2 = rest / 7;
    int pr = t2 % 7;  int b  = t2 / 7;
    const float* base = g_c2 + ((size_t)(b*14 + pr*2)*14 + pc*2)*256 + co;
    float v = fmaxf(fmaxf(base[0], base[256]),
                    fmaxf(base[14*256], base[14*256 + 256]));
    g_feat[idx] = v;
}

// ---------------- encoder matmul: z_e = feat @ enc_w + enc_b ----------------
__global__ void k_enc(const float* __restrict__ ew, const float* __restrict__ eb) {
    __shared__ float fa[8][128];
    __shared__ float wb[128][64];
    int tid = threadIdx.x;
    int b0 = blockIdx.x * 8;
    int frow = tid >> 5, fk = (tid & 31)*4;
    int j4 = tid & 15,  krow = tid >> 4;
    int b_l = tid >> 6, j = tid & 63;
    float acc0 = 0.f, acc1 = 0.f;
    for (int kc = 0; kc < 12544; kc += 128) {
        *reinterpret_cast<float4*>(&fa[frow][fk]) =
            *reinterpret_cast<const float4*>(&g_feat[(size_t)(b0+frow)*12544 + kc + fk]);
#pragma unroll
        for (int i = 0; i < 8; i++) {
            int k = krow + 16*i;
            *reinterpret_cast<float4*>(&wb[k][j4*4]) =
                *reinterpret_cast<const float4*>(&ew[(size_t)(kc+k)*64 + j4*4]);
        }
        __syncthreads();
#pragma unroll 16
        for (int k = 0; k < 128; k++) {
            float w = wb[k][j];
            acc0 = fmaf(fa[b_l][k],   w, acc0);
            acc1 = fmaf(fa[b_l+4][k], w, acc1);
        }
        __syncthreads();
    }
    float bb = eb[j];
    g_z[(b0 + b_l)*64 + j]     = acc0 + bb;
    g_z[(b0 + b_l + 4)*64 + j] = acc1 + bb;
}

// ---------------- SOM: argmin of squared distances, gather z_q ----------------
__global__ void k_som(const float* __restrict__ emb) {
    int b = blockIdx.x, tid = threadIdx.x;
    __shared__ float zs[64];
    __shared__ float ds[256];
    __shared__ int   is[256];
    if (tid < 64) zs[tid] = g_z[b*64 + tid];
    __syncthreads();
    float d = 0.f;
    const float* ep = emb + tid*64;
#pragma unroll 8
    for (int j = 0; j < 64; j++) { float t = zs[j] - ep[j]; d = fmaf(t, t, d); }
    ds[tid] = d; is[tid] = tid;
    __syncthreads();
    for (int s = 128; s > 0; s >>= 1) {
        if (tid < s) {
            float d2 = ds[tid + s];
            if (d2 < ds[tid] || (d2 == ds[tid] && is[tid + s] < is[tid])) {
                ds[tid] = d2; is[tid] = is[tid + s];
            }
        }
        __syncthreads();
    }
    int k = is[0];
    if (tid < 64) g_z[(256 + b)*64 + tid] = emb[k*64 + tid];
}

// ---------------- decoder matmul: dech = z @ dec_w + dec_b (batch 512) ----------------
__global__ void k_dec(const float* __restrict__ dw, const float* __restrict__ db) {
    __shared__ float zs[8][64];
    int tid = threadIdx.x;
    int b0 = blockIdx.x * 8;
    int n  = blockIdx.y * 256 + tid;
#pragma unroll
    for (int i = 0; i < 2; i++) {
        int t = tid + 256*i;
        zs[t >> 6][t & 63] = g_z[(b0 + (t >> 6))*64 + (t & 63)];
    }
    __syncthreads();
    float acc[8];
    float bb = db[n];
#pragma unroll
    for (int i = 0; i < 8; i++) acc[i] = bb;
    for (int k = 0; k < 64; k++) {
        float w = dw[(size_t)k*12544 + n];
#pragma unroll
        for (int i = 0; i < 8; i++) acc[i] = fmaf(zs[i][k], w, acc[i]);
    }
#pragma unroll
    for (int i = 0; i < 8; i++) g_dech[(size_t)(b0 + i)*12544 + n] = acc[i];
}

// ---------------- deconv2 (upsampled 28x28, 256->1) + sigmoid ----------------
__global__ void k_deconv2(const float* __restrict__ dw2,
                          const float* __restrict__ db2,
                          float* __restrict__ out) {
    int bb = blockIdx.x, r = blockIdx.y;
    int t = threadIdx.x;      // channel
    float w3[16];
#pragma unroll
    for (int tap = 0; tap < 16; tap++) w3[tap] = dw2[tap*256 + t];
    float acc[28];
#pragma unroll
    for (int c = 0; c < 28; c++) acc[c] = 0.f;
#pragma unroll
    for (int kh = 0; kh < 4; kh++) {
        int iy = r - 1 + kh;
        if ((unsigned)iy < 28u) {
            int py = iy >> 1;
            const float* rp = g_u1 + ((size_t)(bb*14 + py)*14)*256 + t;
            float v[14];
#pragma unroll
            for (int px = 0; px < 14; px++) v[px] = rp[px*256];
#pragma unroll
            for (int kw = 0; kw < 4; kw++) {
                float wv = w3[kh*4 + kw];
#pragma unroll
                for (int c = 0; c < 28; c++) {
                    int ix = c - 1 + kw;
                    if (ix >= 0 && ix < 28) acc[c] = fmaf(wv, v[ix >> 1], acc[c]);
                }
            }
        }
    }
#pragma unroll
    for (int o = 16; o > 0; o >>= 1)
#pragma unroll
        for (int c = 0; c < 28; c++)
            acc[c] += __shfl_xor_sync(0xffffffffu, acc[c], o);
    __shared__ float red[8][28];
    if ((t & 31) == 0) {
#pragma unroll
        for (int c = 0; c < 28; c++) red[t >> 5][c] = acc[c];
    }
    __syncthreads();
    if (t < 28) {
        float s = db2[0];
#pragma unroll
        for (int w = 0; w < 8; w++) s += red[w][t];
        out[(size_t)bb*784 + r*28 + t] = 1.f / (1.f + expf(-s));
    }
}

// ---------------- launch ----------------
extern "C" void kernel_launch(void* const* d_in, const int* in_sizes, int n_in,
                              void* d_out, int out_size) {
    const float* x   = (const float*)d_in[0];
    const float* c1w = (const float*)d_in[1];
    const float* c1b = (const float*)d_in[2];
    const float* c2w = (const float*)d_in[3];
    const float* c2b = (const float*)d_in[4];
    const float* ew  = (const float*)d_in[5];
    const float* eb  = (const float*)d_in[6];
    const float* emb = (const float*)d_in[7];
    const float* dw  = (const float*)d_in[8];
    const float* db  = (const float*)d_in[9];
    const float* d1w = (const float*)d_in[10];
    const float* d1b = (const float*)d_in[11];
    const float* d2w = (const float*)d_in[12];
    const float* d2b = (const float*)d_in[13];
    float* out = (float*)d_out;

    k_conv1_pool<<<dim3(256, 7), 256>>>(x, c1w, c1b);
    k_conv_gemm<0><<<dim3(392, 2), 256>>>(c2w, c2b);       // conv2 -> g_c2 (relu)
    k_pool2<<<12544, 256>>>();                              // -> g_feat
    k_enc<<<32, 256>>>(ew, eb);                             // -> g_z[0..255]
    k_som<<<256, 256>>>(emb);                               // -> g_z[256..511]
    k_dec<<<dim3(64, 49), 256>>>(dw, db);                   // -> g_dech [512]
    k_conv_gemm<1><<<dim3(784, 2), 256>>>(d1w, d1b);        // deconv1 -> g_u1 (relu)
    k_deconv2<<<dim3(512, 28), 256>>>(d2w, d2b, out);       // -> d_out + sigmoid
}

// round 4
// speedup vs baseline: 1.6279x; 1.6279x over previous
#include <cuda_runtime.h>
#include <math.h>

// ---------------- scratch (device globals; no allocation) ----------------
__device__ float g_p1[256*14*14*256];    // conv1+pool output   [256,14,14,256]
__device__ float g_c2[256*14*14*256];    // conv2 output (relu) [256,14,14,256]
__device__ float g_feat[256*12544];      // pooled+flattened     [256,12544]
__device__ float g_z[512*64];            // rows 0..255: z_e, 256..511: z_q
__device__ float g_dech[512*12544];      // dec matmul output    [512,7,7,256]
__device__ float g_u1[512*14*14*256];    // deconv1 output(relu) [512,14,14,256]
__device__ float g_encp[7*256*64];       // split-K partials for encoder
__device__ float g_wc[6400*256];         // collapsed deconv1 weights, 4 parity classes
// class k-row bases: cls0(3x3):0  cls1(3x2):2304  cls2(2x3):3840  cls3(2x2):5376

// ---------------- conv1 (4x4,1->256, SAME) + relu + maxpool2x2 ----------------
__global__ void k_conv1_pool(const float* __restrict__ x,
                             const float* __restrict__ w1,
                             const float* __restrict__ b1) {
    int b  = blockIdx.x;
    int pr0 = blockIdx.y * 2;
    int co = threadIdx.x;
    __shared__ float xs[784];
    for (int i = threadIdx.x; i < 784; i += 256) xs[i] = x[b*784 + i];
    __syncthreads();
    float w[16];
#pragma unroll
    for (int t = 0; t < 16; t++) w[t] = w1[t*256 + co];
    float bias = b1[co];
    for (int pr = pr0; pr < pr0 + 2; pr++)
        for (int pc = 0; pc < 14; pc++) {
            float m = 0.f;   // max(relu(v)) == max(0, max(v))
#pragma unroll
            for (int dy = 0; dy < 2; dy++)
#pragma unroll
            for (int dx = 0; dx < 2; dx++) {
                int y = pr*2 + dy, xx = pc*2 + dx;
                float s = bias;
#pragma unroll
                for (int kh = 0; kh < 4; kh++) {
                    int iy = y - 1 + kh;
                    if ((unsigned)iy < 28u) {
#pragma unroll
                        for (int kw = 0; kw < 4; kw++) {
                            int ix = xx - 1 + kw;
                            if ((unsigned)ix < 28u)
                                s = fmaf(w[kh*4 + kw], xs[iy*28 + ix], s);
                        }
                    }
                }
                m = fmaxf(m, s);
            }
            g_p1[((b*14 + pr)*14 + pc)*256 + co] = m;
        }
}

// ---------------- implicit-GEMM conv2 (4x4, 256->256, SAME, 14x14) ----------------
__global__ __launch_bounds__(256) void k_conv2_gemm(const float* __restrict__ wt,
                                                    const float* __restrict__ bias) {
    __shared__ float As[2][128*20];   // [m][k] k padded 16->20
    __shared__ float Bs[2][16*128];   // [k][n]

    int tid = threadIdx.x;
    int mt = blockIdx.x, nt = blockIdx.y;

    int a_k4  = tid & 3;
    int a_row = tid >> 2;
    int ar[2], ac[2];
    const float* abase[2];
#pragma unroll
    for (int i = 0; i < 2; i++) {
        int m = mt*128 + a_row + 64*i;
        int b = m / 196; int rem = m - b*196;
        int r = rem / 14; int c = rem - r*14;
        ar[i] = r; ac[i] = c;
        abase[i] = g_p1 + (size_t)b * (14*14*256);
    }
    int b_n4 = tid & 31;
    int b_k  = tid >> 5;
    const float* wbase = wt + nt*128 + b_n4*4;

    int row_t = tid >> 4, col_t = tid & 15;

    float acc[8][8];
#pragma unroll
    for (int e = 0; e < 8; e++)
#pragma unroll
        for (int f = 0; f < 8; f++) acc[e][f] = 0.f;

    float4 av[2], bv[2];
    auto doLoad = [&](int kt) {
        int khw = kt >> 4, kh = khw >> 2, kw = khw & 3;
        int cib = (kt & 15)*16 + a_k4*4;
#pragma unroll
        for (int i = 0; i < 2; i++) {
            int iy = ar[i] - 1 + kh, ix = ac[i] - 1 + kw;
            float4 v = make_float4(0.f, 0.f, 0.f, 0.f);
            if (((unsigned)iy < 14u) && ((unsigned)ix < 14u))
                v = *reinterpret_cast<const float4*>(
                        abase[i] + (iy*14 + ix)*256 + cib);
            av[i] = v;
        }
        const float* p = wbase + (kt*16 + b_k)*256;
        bv[0] = *reinterpret_cast<const float4*>(p);
        bv[1] = *reinterpret_cast<const float4*>(p + 8*256);
    };
    auto doStore = [&](int buf) {
        *reinterpret_cast<float4*>(&As[buf][a_row*20 + a_k4*4])       = av[0];
        *reinterpret_cast<float4*>(&As[buf][(a_row+64)*20 + a_k4*4])  = av[1];
        *reinterpret_cast<float4*>(&Bs[buf][b_k*128 + b_n4*4])        = bv[0];
        *reinterpret_cast<float4*>(&Bs[buf][(b_k+8)*128 + b_n4*4])    = bv[1];
    };

    doLoad(0); doStore(0); __syncthreads();

    for (int kt = 0; kt < 256; kt++) {
        int cur = kt & 1;
        if (kt < 255) doLoad(kt + 1);
#pragma unroll
        for (int k = 0; k < 16; k++) {
            float a[8], bb[8];
#pragma unroll
            for (int e = 0; e < 4; e++) {
                a[e]   = As[cur][(row_t*4 + e)*20 + k];
                a[4+e] = As[cur][(64 + row_t*4 + e)*20 + k];
            }
            float4 q0 = *reinterpret_cast<const float4*>(&Bs[cur][k*128 + col_t*4]);
            float4 q1 = *reinterpret_cast<const float4*>(&Bs[cur][k*128 + 64 + col_t*4]);
            bb[0]=q0.x; bb[1]=q0.y; bb[2]=q0.z; bb[3]=q0.w;
            bb[4]=q1.x; bb[5]=q1.y; bb[6]=q1.z; bb[7]=q1.w;
#pragma unroll
            for (int e = 0; e < 8; e++)
#pragma unroll
                for (int f = 0; f < 8; f++)
                    acc[e][f] = fmaf(a[e], bb[f], acc[e][f]);
        }
        if (kt < 255) { doStore(cur ^ 1); __syncthreads(); }
    }

    int m0 = mt*128;
#pragma unroll
    for (int e = 0; e < 8; e++) {
        int mrow = m0 + ((e < 4) ? (row_t*4 + e) : (64 + row_t*4 + e - 4));
        float* op = g_c2 + (size_t)mrow*256 + nt*128;
#pragma unroll
        for (int h = 0; h < 2; h++) {
            int n0 = h*64 + col_t*4;
            float4 bz = *reinterpret_cast<const float4*>(bias + nt*128 + n0);
            float4 v;
            v.x = fmaxf(acc[e][h*4+0] + bz.x, 0.f);
            v.y = fmaxf(acc[e][h*4+1] + bz.y, 0.f);
            v.z = fmaxf(acc[e][h*4+2] + bz.z, 0.f);
            v.w = fmaxf(acc[e][h*4+3] + bz.w, 0.f);
            *reinterpret_cast<float4*>(op + n0) = v;
        }
    }
}

// ---------------- collapse deconv1 weights into parity classes ----------------
// even output coord 2t:   taps over source {t-1, t, t+1} with weights {w0, w1+w2, w3}
// odd  output coord 2t+1: taps over source {t, t+1}       with weights {w0+w1, w2+w3}
__global__ void k_prep_w(const float* __restrict__ w) {
    int row = blockIdx.x;         // 0..6399 collapsed k-row
    int co  = threadIdx.x;        // 0..255
    int cls, base;
    if (row < 2304)      { cls = 0; base = 0; }
    else if (row < 3840) { cls = 1; base = 2304; }
    else if (row < 5376) { cls = 2; base = 3840; }
    else                 { cls = 3; base = 5376; }
    int py = cls >> 1, px = cls & 1;
    int TW = 3 - px;
    int r = row - base;
    int tap = r >> 8, ci = r & 255;
    int oyi = tap / TW, oxi = tap - oyi*TW;
    const int mt0[3] = {1, 6, 8};     // parity 0: kh sets {0},{1,2},{3}
    const int mt1[3] = {3, 12, 0};    // parity 1: kh sets {0,1},{2,3}
    int mR = py ? mt1[oyi] : mt0[oyi];
    int mC = px ? mt1[oxi] : mt0[oxi];
    float s = 0.f;
#pragma unroll
    for (int kh = 0; kh < 4; kh++) if ((mR >> kh) & 1)
#pragma unroll
        for (int kw = 0; kw < 4; kw++) if ((mC >> kw) & 1)
            s += w[((kh*4 + kw)*256 + ci)*256 + co];
    g_wc[(size_t)row*256 + co] = s;
}

// ---------------- deconv1 as 4 parity-class implicit GEMMs over 7x7 source ----------------
// blockIdx.z = class; M = 512*49 = 25088; N = 256; K = TH*TW*256
__global__ __launch_bounds__(256) void k_deconv1_gemm(const float* __restrict__ bias) {
    int cls = blockIdx.z;
    int py = cls >> 1, px = cls & 1;
    int TH = 3 - py, TW = 3 - px;
    int ktiles = TH * TW * 16;
    int kbase = (cls == 0) ? 0 : (cls == 1) ? 2304 : (cls == 2) ? 3840 : 5376;

    __shared__ float As[2][128*20];
    __shared__ float Bs[2][16*128];
    __shared__ int s_offR[9], s_offC[9];

    int tid = threadIdx.x;
    if (tid < TH*TW) {
        int oyi = tid / TW, oxi = tid - (tid / TW)*TW;
        s_offR[tid] = oyi - (1 - py);
        s_offC[tid] = oxi - (1 - px);
    }

    int mt = blockIdx.x, nt = blockIdx.y;
    int a_k4  = tid & 3;
    int a_row = tid >> 2;
    int at[2], au[2];
    const float* abase[2];
#pragma unroll
    for (int i = 0; i < 2; i++) {
        int m = mt*128 + a_row + 64*i;
        int b = m / 49; int rem = m - b*49;
        at[i] = rem / 7; au[i] = rem - (rem/7)*7;
        abase[i] = g_dech + (size_t)b * 12544;
    }
    int b_n4 = tid & 31;
    int b_k  = tid >> 5;
    const float* wbase = g_wc + (size_t)kbase*256 + nt*128 + b_n4*4;

    int row_t = tid >> 4, col_t = tid & 15;

    float acc[8][8];
#pragma unroll
    for (int e = 0; e < 8; e++)
#pragma unroll
        for (int f = 0; f < 8; f++) acc[e][f] = 0.f;

    __syncthreads();  // s_offR/s_offC visible

    float4 av[2], bv[2];
    auto doLoad = [&](int kt) {
        int tap = kt >> 4;
        int oR = s_offR[tap], oC = s_offC[tap];
        int cib = (kt & 15)*16 + a_k4*4;
#pragma unroll
        for (int i = 0; i < 2; i++) {
            int sy = at[i] + oR, sx = au[i] + oC;
            float4 v = make_float4(0.f, 0.f, 0.f, 0.f);
            if (((unsigned)sy < 7u) && ((unsigned)sx < 7u))
                v = *reinterpret_cast<const float4*>(abase[i] + (sy*7 + sx)*256 + cib);
            av[i] = v;
        }
        const float* p = wbase + (size_t)(kt*16 + b_k)*256;
        bv[0] = *reinterpret_cast<const float4*>(p);
        bv[1] = *reinterpret_cast<const float4*>(p + 8*256);
    };
    auto doStore = [&](int buf) {
        *reinterpret_cast<float4*>(&As[buf][a_row*20 + a_k4*4])       = av[0];
        *reinterpret_cast<float4*>(&As[buf][(a_row+64)*20 + a_k4*4])  = av[1];
        *reinterpret_cast<float4*>(&Bs[buf][b_k*128 + b_n4*4])        = bv[0];
        *reinterpret_cast<float4*>(&Bs[buf][(b_k+8)*128 + b_n4*4])    = bv[1];
    };

    doLoad(0); doStore(0); __syncthreads();

    for (int kt = 0; kt < ktiles; kt++) {
        int cur = kt & 1;
        if (kt + 1 < ktiles) doLoad(kt + 1);
#pragma unroll
        for (int k = 0; k < 16; k++) {
            float a[8], bb[8];
#pragma unroll
            for (int e = 0; e < 4; e++) {
                a[e]   = As[cur][(row_t*4 + e)*20 + k];
                a[4+e] = As[cur][(64 + row_t*4 + e)*20 + k];
            }
            float4 q0 = *reinterpret_cast<const float4*>(&Bs[cur][k*128 + col_t*4]);
            float4 q1 = *reinterpret_cast<const float4*>(&Bs[cur][k*128 + 64 + col_t*4]);
            bb[0]=q0.x; bb[1]=q0.y; bb[2]=q0.z; bb[3]=q0.w;
            bb[4]=q1.x; bb[5]=q1.y; bb[6]=q1.z; bb[7]=q1.w;
#pragma unroll
            for (int e = 0; e < 8; e++)
#pragma unroll
                for (int f = 0; f < 8; f++)
                    acc[e][f] = fmaf(a[e], bb[f], acc[e][f]);
        }
        if (kt + 1 < ktiles) { doStore(cur ^ 1); __syncthreads(); }
    }

    int m0 = mt*128;
#pragma unroll
    for (int e = 0; e < 8; e++) {
        int mrow = m0 + ((e < 4) ? (row_t*4 + e) : (64 + row_t*4 + e - 4));
        int b = mrow / 49; int rem = mrow - b*49;
        int t = rem / 7, u = rem - (rem/7)*7;
        float* op = g_u1 + ((size_t)((b*14 + 2*t + py)*14) + 2*u + px)*256 + nt*128;
#pragma unroll
        for (int h = 0; h < 2; h++) {
            int n0 = h*64 + col_t*4;
            float4 bz = *reinterpret_cast<const float4*>(bias + nt*128 + n0);
            float4 v;
            v.x = fmaxf(acc[e][h*4+0] + bz.x, 0.f);
            v.y = fmaxf(acc[e][h*4+1] + bz.y, 0.f);
            v.z = fmaxf(acc[e][h*4+2] + bz.z, 0.f);
            v.w = fmaxf(acc[e][h*4+3] + bz.w, 0.f);
            *reinterpret_cast<float4*>(op + n0) = v;
        }
    }
}

// ---------------- maxpool 14->7 + flatten ----------------
__global__ void k_pool2() {
    int idx = blockIdx.x*256 + threadIdx.x;     // 256*49*256 total
    int co = idx & 255;
    int rest = idx >> 8;
    int pc = rest % 7; int t2 = rest / 7;
    int pr = t2 % 7;  int b  = t2 / 7;
    const float* base = g_c2 + ((size_t)(b*14 + pr*2)*14 + pc*2)*256 + co;
    float v = fmaxf(fmaxf(base[0], base[256]),
                    fmaxf(base[14*256], base[14*256 + 256]));
    g_feat[idx] = v;
}

// ---------------- encoder matmul: split-K partials ----------------
__global__ void k_enc(const float* __restrict__ ew) {
    __shared__ float fa[8][128];
    __shared__ float wb[128][64];
    int tid = threadIdx.x;
    int b0 = blockIdx.x * 8;
    int kc0 = blockIdx.y * 1792;
    int frow = tid >> 5, fk = (tid & 31)*4;
    int j4 = tid & 15,  krow = tid >> 4;
    int b_l = tid >> 6, j = tid & 63;
    float acc0 = 0.f, acc1 = 0.f;
    for (int kc = kc0; kc < kc0 + 1792; kc += 128) {
        *reinterpret_cast<float4*>(&fa[frow][fk]) =
            *reinterpret_cast<const float4*>(&g_feat[(size_t)(b0+frow)*12544 + kc + fk]);
#pragma unroll
        for (int i = 0; i < 8; i++) {
            int k = krow + 16*i;
            *reinterpret_cast<float4*>(&wb[k][j4*4]) =
                *reinterpret_cast<const float4*>(&ew[(size_t)(kc+k)*64 + j4*4]);
        }
        __syncthreads();
#pragma unroll 16
        for (int k = 0; k < 128; k++) {
            float w = wb[k][j];
            acc0 = fmaf(fa[b_l][k],   w, acc0);
            acc1 = fmaf(fa[b_l+4][k], w, acc1);
        }
        __syncthreads();
    }
    float* pp = g_encp + (size_t)blockIdx.y*16384;
    pp[(b0 + b_l)*64 + j]     = acc0;
    pp[(b0 + b_l + 4)*64 + j] = acc1;
}

__global__ void k_enc_red(const float* __restrict__ eb) {
    int idx = blockIdx.x*256 + threadIdx.x;   // 16384
    float s = eb[idx & 63];
#pragma unroll
    for (int p = 0; p < 7; p++) s += g_encp[p*16384 + idx];
    g_z[idx] = s;
}

// ---------------- SOM: argmin of squared distances, gather z_q ----------------
__global__ void k_som(const float* __restrict__ emb) {
    int b = blockIdx.x, tid = threadIdx.x;
    __shared__ float zs[64];
    __shared__ float ds[256];
    __shared__ int   is[256];
    if (tid < 64) zs[tid] = g_z[b*64 + tid];
    __syncthreads();
    float d = 0.f;
    const float* ep = emb + tid*64;
#pragma unroll 8
    for (int j = 0; j < 64; j++) { float t = zs[j] - ep[j]; d = fmaf(t, t, d); }
    ds[tid] = d; is[tid] = tid;
    __syncthreads();
    for (int s = 128; s > 0; s >>= 1) {
        if (tid < s) {
            float d2 = ds[tid + s];
            if (d2 < ds[tid] || (d2 == ds[tid] && is[tid + s] < is[tid])) {
                ds[tid] = d2; is[tid] = is[tid + s];
            }
        }
        __syncthreads();
    }
    int k = is[0];
    if (tid < 64) g_z[(256 + b)*64 + tid] = emb[k*64 + tid];
}

// ---------------- decoder matmul: dech = z @ dec_w + dec_b (batch 512) ----------------
__global__ void k_dec(const float* __restrict__ dw, const float* __restrict__ db) {
    __shared__ float zs[8][64];
    int tid = threadIdx.x;
    int b0 = blockIdx.x * 8;
    int n  = blockIdx.y * 256 + tid;
#pragma unroll
    for (int i = 0; i < 2; i++) {
        int t = tid + 256*i;
        zs[t >> 6][t & 63] = g_z[(b0 + (t >> 6))*64 + (t & 63)];
    }
    __syncthreads();
    float acc[8];
    float bb = db[n];
#pragma unroll
    for (int i = 0; i < 8; i++) acc[i] = bb;
    for (int k = 0; k < 64; k++) {
        float w = dw[(size_t)k*12544 + n];
#pragma unroll
        for (int i = 0; i < 8; i++) acc[i] = fmaf(zs[i][k], w, acc[i]);
    }
#pragma unroll
    for (int i = 0; i < 8; i++) g_dech[(size_t)(b0 + i)*12544 + n] = acc[i];
}

// ---------------- deconv2 (upsampled 28x28, 256->1) + sigmoid ----------------
__global__ void k_deconv2(const float* __restrict__ dw2,
                          const float* __restrict__ db2,
                          float* __restrict__ out) {
    int bb = blockIdx.x, r = blockIdx.y;
    int t = threadIdx.x;      // channel
    float w3[16];
#pragma unroll
    for (int tap = 0; tap < 16; tap++) w3[tap] = dw2[tap*256 + t];
    float acc[28];
#pragma unroll
    for (int c = 0; c < 28; c++) acc[c] = 0.f;
#pragma unroll
    for (int kh = 0; kh < 4; kh++) {
        int iy = r - 1 + kh;
        if ((unsigned)iy < 28u) {
            int py = iy >> 1;
            const float* rp = g_u1 + ((size_t)(bb*14 + py)*14)*256 + t;
            float v[14];
#pragma unroll
            for (int px = 0; px < 14; px++) v[px] = rp[px*256];
#pragma unroll
            for (int kw = 0; kw < 4; kw++) {
                float wv = w3[kh*4 + kw];
#pragma unroll
                for (int c = 0; c < 28; c++) {
                    int ix = c - 1 + kw;
                    if (ix >= 0 && ix < 28) acc[c] = fmaf(wv, v[ix >> 1], acc[c]);
                }
            }
        }
    }
#pragma unroll
    for (int o = 16; o > 0; o >>= 1)
#pragma unroll
        for (int c = 0; c < 28; c++)
            acc[c] += __shfl_xor_sync(0xffffffffu, acc[c], o);
    __shared__ float red[8][28];
    if ((t & 31) == 0) {
#pragma unroll
        for (int c = 0; c < 28; c++) red[t >> 5][c] = acc[c];
    }
    __syncthreads();
    if (t < 28) {
        float s = db2[0];
#pragma unroll
        for (int w = 0; w < 8; w++) s += red[w][t];
        out[(size_t)bb*784 + r*28 + t] = 1.f / (1.f + expf(-s));
    }
}

// ---------------- launch ----------------
extern "C" void kernel_launch(void* const* d_in, const int* in_sizes, int n_in,
                              void* d_out, int out_size) {
    const float* x   = (const float*)d_in[0];
    const float* c1w = (const float*)d_in[1];
    const float* c1b = (const float*)d_in[2];
    const float* c2w = (const float*)d_in[3];
    const float* c2b = (const float*)d_in[4];
    const float* ew  = (const float*)d_in[5];
    const float* eb  = (const float*)d_in[6];
    const float* emb = (const float*)d_in[7];
    const float* dw  = (const float*)d_in[8];
    const float* db  = (const float*)d_in[9];
    const float* d1w = (const float*)d_in[10];
    const float* d1b = (const float*)d_in[11];
    const float* d2w = (const float*)d_in[12];
    const float* d2b = (const float*)d_in[13];
    float* out = (float*)d_out;

    k_prep_w<<<6400, 256>>>(d1w);                           // collapsed deconv1 weights
    k_conv1_pool<<<dim3(256, 7), 256>>>(x, c1w, c1b);
    k_conv2_gemm<<<dim3(392, 2), 256>>>(c2w, c2b);          // conv2 -> g_c2 (relu)
    k_pool2<<<12544, 256>>>();                               // -> g_feat
    k_enc<<<dim3(32, 7), 256>>>(ew);                         // split-K partials
    k_enc_red<<<64, 256>>>(eb);                              // -> g_z[0..255]
    k_som<<<256, 256>>>(emb);                                // -> g_z[256..511]
    k_dec<<<dim3(64, 49), 256>>>(dw, db);                    // -> g_dech [512]
    k_deconv1_gemm<<<dim3(196, 2, 4), 256>>>(d1b);           // parity GEMMs -> g_u1 (relu)
    k_deconv2<<<dim3(512, 28), 256>>>(d2w, d2b, out);        // -> d_out + sigmoid
}